// round 2
// baseline (speedup 1.0000x reference)
#include <cuda_runtime.h>
#include <cstdint>

#define NB 256
#define NS 2048
#define NK 64

// Scratch (device globals — no allocation allowed)
__device__ float g_vecA[NB][NK];
__device__ float g_vecB[NB][NK];
__device__ float g_offA[NB];
__device__ float g_offB[NB];
__device__ float g_gold[NB];

typedef unsigned long long u64;

__device__ __forceinline__ u64 fma2(u64 a, u64 b, u64 c) {
    u64 d; asm("fma.rn.f32x2 %0, %1, %2, %3;" : "=l"(d) : "l"(a), "l"(b), "l"(c)); return d;
}
__device__ __forceinline__ u64 add2(u64 a, u64 b) {
    u64 d; asm("add.rn.f32x2 %0, %1, %2;" : "=l"(d) : "l"(a), "l"(b)); return d;
}
__device__ __forceinline__ u64 pack2(float x, float y) {
    u64 d; asm("mov.b64 %0, {%1, %2};" : "=l"(d) : "f"(x), "f"(y)); return d;
}
__device__ __forceinline__ float2 unpack2(u64 v) {
    float2 f; asm("mov.b64 {%0, %1}, %2;" : "=f"(f.x), "=f"(f.y) : "l"(v)); return f;
}

// z[pair] = sum_i a_dup[i] * Er[i]   (64 fma.f32x2, 4 independent chains)
__device__ __forceinline__ float2 matvec64(const u64* __restrict__ q, const u64 (&Er)[NK]) {
    u64 c0 = 0, c1 = 0, c2 = 0, c3 = 0;
    #pragma unroll
    for (int gg = 0; gg < 16; gg++) {
        c0 = fma2(q[4 * gg + 0], Er[4 * gg + 0], c0);
        c1 = fma2(q[4 * gg + 1], Er[4 * gg + 1], c1);
        c2 = fma2(q[4 * gg + 2], Er[4 * gg + 2], c2);
        c3 = fma2(q[4 * gg + 3], Er[4 * gg + 3], c3);
    }
    return unpack2(add2(add2(c0, c1), add2(c2, c3)));
}

// Exact power-of-two rescale; offset tracked in log domain.
__device__ __forceinline__ void rescale2(float& x, float& y, float& off) {
    float m = fmaxf(x, y);
    #pragma unroll
    for (int d = 16; d; d >>= 1) m = fmaxf(m, __shfl_xor_sync(0xffffffffu, m, d));
    int k = (__float_as_int(m) >> 23) - 127;
    float scl = __int_as_float((127 - k) << 23);   // 2^-k
    x *= scl; y *= scl;
    off += (float)k * 0.69314718055994531f;
}

// ---- forward step macros (read QS, write DS, dup-pair layout) ----
#define FSTEP(BUF, QS, DS) do {                                         \
    float2 sv_ = BUF; BUF = *pre; pre += 32;                            \
    float ex0_ = __expf(sv_.x), ex1_ = __expf(sv_.y);                   \
    float2 z_ = matvec64(QS, Er);                                       \
    a.x = z_.x * ex0_; a.y = z_.y * ex1_;                               \
    DS[2 * l] = pack2(a.x, a.x); DS[2 * l + 1] = pack2(a.y, a.y);       \
    __syncwarp();                                                       \
} while (0)

#define FSTEP_R(BUF, QS, DS) do {                                       \
    float2 sv_ = BUF; BUF = *pre; pre += 32;                            \
    float ex0_ = __expf(sv_.x), ex1_ = __expf(sv_.y);                   \
    float2 z_ = matvec64(QS, Er);                                       \
    a.x = z_.x * ex0_; a.y = z_.y * ex1_;                               \
    rescale2(a.x, a.y, off);                                            \
    DS[2 * l] = pack2(a.x, a.x); DS[2 * l + 1] = pack2(a.y, a.y);       \
    __syncwarp();                                                       \
} while (0)

// ---- backward step macros (write S then matvec-read S) ----
#define BSTEP(BUF, S) do {                                              \
    float2 sv_ = BUF; BUF = *pre; pre -= 32;                            \
    float w0_ = a.x * __expf(sv_.x), w1_ = a.y * __expf(sv_.y);         \
    S[2 * l] = pack2(w0_, w0_); S[2 * l + 1] = pack2(w1_, w1_);         \
    __syncwarp();                                                       \
    a = matvec64(S, Er);                                                \
} while (0)

#define BSTEP_R(BUF, S) do {                                            \
    float2 sv_ = BUF; BUF = *pre; pre -= 32;                            \
    float w0_ = a.x * __expf(sv_.x), w1_ = a.y * __expf(sv_.y);         \
    rescale2(w0_, w1_, off);                                            \
    S[2 * l] = pack2(w0_, w0_); S[2 * l + 1] = pack2(w1_, w1_);         \
    __syncwarp();                                                       \
    a = matvec64(S, Er);                                                \
} while (0)

// Blocks [0,128): 4 warps x one half-chain each (512 half-chains).
// Blocks [128,192): 4 warps x one gold-path batch each (256 batches).
__global__ void __launch_bounds__(128)
crf_fused(const float* __restrict__ scores, const int* __restrict__ states,
          const float* __restrict__ trans, const float* __restrict__ source,
          const float* __restrict__ sink)
{
    const int w = threadIdx.x >> 5;
    const int l = threadIdx.x & 31;

    if (blockIdx.x >= 128) {
        // ---------------- gold path (one warp per batch) ----------------
        const int b = (blockIdx.x - 128) * 4 + w;
        const int* st = states + b * NS;
        const float* sc = scores + (size_t)b * NS * NK;
        float acc = 0.f;
        #pragma unroll 4
        for (int t = l; t < NS; t += 32) {
            int s = st[t];
            float e = sc[t * NK + s];
            float tr = (t + 1 < NS) ? trans[s * NK + st[t + 1]] : 0.f;
            acc += e + tr;
        }
        #pragma unroll
        for (int d = 16; d; d >>= 1) acc += __shfl_xor_sync(0xffffffffu, acc, d);
        if (l == 0) g_gold[b] = acc + source[st[0]] + sink[st[NS - 1]];
        return;
    }

    // ---------------- chains ----------------
    __shared__ u64 sh[4][2][NK];   // [warp][double-buffer][dup-pair]
    const int g = blockIdx.x * 4 + w;
    const int b = g >> 1;
    const bool fwd = (g & 1) == 0;

    u64 Er[NK];
    if (fwd) {
        #pragma unroll
        for (int i = 0; i < NK; i++) {
            float2 tv = ((const float2*)(trans + i * NK))[l];
            Er[i] = pack2(expf(tv.x), expf(tv.y));
        }
    } else {
        #pragma unroll
        for (int j = 0; j < NK; j++) {
            Er[j] = pack2(expf(trans[(2 * l) * NK + j]),
                          expf(trans[(2 * l + 1) * NK + j]));
        }
    }

    const float2* sp = (const float2*)(scores + (size_t)b * NS * NK) + l;
    u64* sA = sh[w][0];
    u64* sB = sh[w][1];
    float off = 0.f;
    float2 a;

    if (fwd) {
        float2 s0v = sp[0];
        a.x = expf(source[2 * l] + s0v.x);
        a.y = expf(source[2 * l + 1] + s0v.y);
        sA[2 * l] = pack2(a.x, a.x);
        sA[2 * l + 1] = pack2(a.y, a.y);
        __syncwarp();

        float2 buf0 = sp[1 * 32], buf1 = sp[2 * 32], buf2 = sp[3 * 32], buf3 = sp[4 * 32];
        const float2* pre = sp + 5 * 32;

        // t = 1..1020 in 255 static groups of 4 (rescale on the 4th step)
        #pragma unroll 1
        for (int grp = 0; grp < 255; grp++) {
            FSTEP  (buf0, sA, sB);
            FSTEP  (buf1, sB, sA);
            FSTEP  (buf2, sA, sB);
            FSTEP_R(buf3, sB, sA);
        }
        // tail t = 1021..1023 (3 steps, no rescale needed)
        FSTEP(buf0, sA, sB);
        FSTEP(buf1, sB, sA);
        FSTEP(buf2, sA, sB);

        g_vecA[b][2 * l] = a.x;
        g_vecA[b][2 * l + 1] = a.y;
        if (l == 0) g_offA[b] = off;
    } else {
        a.x = expf(sink[2 * l]);
        a.y = expf(sink[2 * l + 1]);

        float2 buf0 = sp[2047 * 32], buf1 = sp[2046 * 32], buf2 = sp[2045 * 32], buf3 = sp[2044 * 32];
        const float2* pre = sp + 2043 * 32;

        // n = 0..1023 in 256 static groups of 4 (rescale on the 4th step)
        #pragma unroll 1
        for (int grp = 0; grp < 256; grp++) {
            BSTEP  (buf0, sA);
            BSTEP  (buf1, sB);
            BSTEP  (buf2, sA);
            BSTEP_R(buf3, sB);
        }

        g_vecB[b][2 * l] = a.x;
        g_vecB[b][2 * l + 1] = a.y;
        if (l == 0) g_offB[b] = off;
    }
}

// loss_b = log(sum_j A[b][j]*B[b][j]) + offA + offB - gold ; out = mean
__global__ void crf_combine(float* __restrict__ out)
{
    const int b = threadIdx.x;   // 256 threads
    float s = 0.f;
    #pragma unroll
    for (int j = 0; j < NK; j++) s += g_vecA[b][j] * g_vecB[b][j];
    float loss = logf(s) + g_offA[b] + g_offB[b] - g_gold[b];

    __shared__ float red[256];
    red[b] = loss;
    __syncthreads();
    #pragma unroll
    for (int k = 128; k; k >>= 1) {
        if (b < k) red[b] += red[b + k];
        __syncthreads();
    }
    if (b == 0) out[0] = red[0] * (1.0f / NB);
}

extern "C" void kernel_launch(void* const* d_in, const int* in_sizes, int n_in,
                              void* d_out, int out_size)
{
    const float* scores = (const float*)d_in[0];
    const int*   states = (const int*)d_in[1];
    const float* trans  = (const float*)d_in[2];
    const float* source = (const float*)d_in[3];
    const float* sink   = (const float*)d_in[4];

    crf_fused<<<192, 128>>>(scores, states, trans, source, sink);
    crf_combine<<<1, 256>>>((float*)d_out);
}

// round 3
// speedup vs baseline: 1.3235x; 1.3235x over previous
#include <cuda_runtime.h>
#include <cstdint>

#define NB 256
#define NS 2048
#define NK 64

// Scratch (device globals — no allocation allowed)
__device__ float g_vecA[NB][NK];
__device__ float g_vecB[NB][NK];
__device__ float g_offA[NB];
__device__ float g_offB[NB];
__device__ float g_gold[NB];

typedef unsigned long long u64;

__device__ __forceinline__ u64 fma2(u64 a, u64 b, u64 c) {
    u64 d; asm("fma.rn.f32x2 %0, %1, %2, %3;" : "=l"(d) : "l"(a), "l"(b), "l"(c)); return d;
}
__device__ __forceinline__ u64 add2(u64 a, u64 b) {
    u64 d; asm("add.rn.f32x2 %0, %1, %2;" : "=l"(d) : "l"(a), "l"(b)); return d;
}
__device__ __forceinline__ u64 pack2(float x, float y) {
    u64 d; asm("mov.b64 %0, {%1, %2};" : "=l"(d) : "f"(x), "f"(y)); return d;
}
__device__ __forceinline__ float2 unpack2(u64 v) {
    float2 f; asm("mov.b64 {%0, %1}, %2;" : "=f"(f.x), "=f"(f.y) : "l"(v)); return f;
}

// z[pair] = sum_i a_dup[i] * Er[i]  — 32x LDS.128, 64x fma.f32x2, 4 acc chains
__device__ __forceinline__ float2 matvec64(const u64* __restrict__ s, const u64 (&Er)[NK]) {
    const ulonglong2* q = (const ulonglong2*)s;
    u64 c0 = 0, c1 = 0, c2 = 0, c3 = 0;
    #pragma unroll
    for (int gg = 0; gg < 16; gg++) {
        ulonglong2 p0 = q[2 * gg];
        ulonglong2 p1 = q[2 * gg + 1];
        c0 = fma2(p0.x, Er[4 * gg],     c0);
        c1 = fma2(p0.y, Er[4 * gg + 1], c1);
        c2 = fma2(p1.x, Er[4 * gg + 2], c2);
        c3 = fma2(p1.y, Er[4 * gg + 3], c3);
    }
    return unpack2(add2(add2(c0, c1), add2(c2, c3)));
}

// Exact power-of-two rescale; offset tracked in log domain.
__device__ __forceinline__ void rescale2(float& x, float& y, float& off) {
    float m = fmaxf(x, y);
    #pragma unroll
    for (int d = 16; d; d >>= 1) m = fmaxf(m, __shfl_xor_sync(0xffffffffu, m, d));
    int k = (__float_as_int(m) >> 23) - 127;
    float scl = __int_as_float((127 - k) << 23);   // 2^-k
    x *= scl; y *= scl;
    off += (float)k * 0.69314718055994531f;
}

// ---- forward step (read QS, write DS, dup-pair layout) ----
#define FSTEP(BUF, QS, DS) do {                                         \
    float2 sv_ = BUF; BUF = *pre; pre += 32;                            \
    float ex0_ = __expf(sv_.x), ex1_ = __expf(sv_.y);                   \
    float2 z_ = matvec64(QS, Er);                                       \
    a.x = z_.x * ex0_; a.y = z_.y * ex1_;                               \
    DS[2 * l] = pack2(a.x, a.x); DS[2 * l + 1] = pack2(a.y, a.y);       \
    __syncwarp();                                                       \
} while (0)

#define FSTEP_R(BUF, QS, DS) do {                                       \
    float2 sv_ = BUF; BUF = *pre; pre += 32;                            \
    float ex0_ = __expf(sv_.x), ex1_ = __expf(sv_.y);                   \
    float2 z_ = matvec64(QS, Er);                                       \
    a.x = z_.x * ex0_; a.y = z_.y * ex1_;                               \
    rescale2(a.x, a.y, off);                                            \
    DS[2 * l] = pack2(a.x, a.x); DS[2 * l + 1] = pack2(a.y, a.y);       \
    __syncwarp();                                                       \
} while (0)

// ---- backward step (write S then matvec-read S) ----
#define BSTEP(BUF, S) do {                                              \
    float2 sv_ = BUF; BUF = *pre; pre -= 32;                            \
    float w0_ = a.x * __expf(sv_.x), w1_ = a.y * __expf(sv_.y);         \
    S[2 * l] = pack2(w0_, w0_); S[2 * l + 1] = pack2(w1_, w1_);         \
    __syncwarp();                                                       \
    a = matvec64(S, Er);                                                \
} while (0)

#define BSTEP_R(BUF, S) do {                                            \
    float2 sv_ = BUF; BUF = *pre; pre -= 32;                            \
    float w0_ = a.x * __expf(sv_.x), w1_ = a.y * __expf(sv_.y);         \
    rescale2(w0_, w1_, off);                                            \
    S[2 * l] = pack2(w0_, w0_); S[2 * l + 1] = pack2(w1_, w1_);         \
    __syncwarp();                                                       \
    a = matvec64(S, Er);                                                \
} while (0)

// Blocks [0,64): 8 warps x one half-chain each (512 half-chains).
//   -> 2 chain warps per SMSP: warp B's fma2 issues while warp A waits on LDS.
// Blocks [64,96): 8 warps x one gold-path batch each (256 batches).
// 96 blocks total: single wave on 148 SMs, no chains co-location.
__global__ void __launch_bounds__(256, 1)
crf_fused(const float* __restrict__ scores, const int* __restrict__ states,
          const float* __restrict__ trans, const float* __restrict__ source,
          const float* __restrict__ sink)
{
    const int w = threadIdx.x >> 5;
    const int l = threadIdx.x & 31;

    if (blockIdx.x >= 64) {
        // ---------------- gold path (one warp per batch) ----------------
        const int b = (blockIdx.x - 64) * 8 + w;
        const int* st = states + b * NS;
        const float* sc = scores + (size_t)b * NS * NK;
        float acc = 0.f;
        #pragma unroll 4
        for (int t = l; t < NS; t += 32) {
            int s = st[t];
            float e = sc[t * NK + s];
            float tr = (t + 1 < NS) ? trans[s * NK + st[t + 1]] : 0.f;
            acc += e + tr;
        }
        #pragma unroll
        for (int d = 16; d; d >>= 1) acc += __shfl_xor_sync(0xffffffffu, acc, d);
        if (l == 0) g_gold[b] = acc + source[st[0]] + sink[st[NS - 1]];
        return;
    }

    // ---------------- chains ----------------
    __shared__ u64 sh[8][2][NK];   // [warp][double-buffer][dup-pair]  8KB
    const int g = blockIdx.x * 8 + w;
    const int b = g >> 1;
    const bool fwd = (g & 1) == 0;

    u64 Er[NK];
    if (fwd) {
        // Er[i] = (exp(T[i][2l]), exp(T[i][2l+1]))  (column pair)
        #pragma unroll
        for (int i = 0; i < NK; i++) {
            float2 tv = ((const float2*)(trans + i * NK))[l];
            Er[i] = pack2(expf(tv.x), expf(tv.y));
        }
    } else {
        // Er[j] = (exp(T[2l][j]), exp(T[2l+1][j]))  (row pair)
        #pragma unroll
        for (int j = 0; j < NK; j++) {
            Er[j] = pack2(expf(trans[(2 * l) * NK + j]),
                          expf(trans[(2 * l + 1) * NK + j]));
        }
    }

    const float2* sp = (const float2*)(scores + (size_t)b * NS * NK) + l;
    u64* sA = sh[w][0];
    u64* sB = sh[w][1];
    float off = 0.f;
    float2 a;

    if (fwd) {
        // alpha_0 = exp(source + scores[b,0,:])
        float2 s0v = sp[0];
        a.x = expf(source[2 * l] + s0v.x);
        a.y = expf(source[2 * l + 1] + s0v.y);
        sA[2 * l] = pack2(a.x, a.x);
        sA[2 * l + 1] = pack2(a.y, a.y);
        __syncwarp();

        float2 buf0 = sp[1 * 32], buf1 = sp[2 * 32], buf2 = sp[3 * 32], buf3 = sp[4 * 32];
        const float2* pre = sp + 5 * 32;

        // t = 1..1020: 255 static groups of 4 (rescale on 4th step)
        #pragma unroll 1
        for (int grp = 0; grp < 255; grp++) {
            FSTEP  (buf0, sA, sB);
            FSTEP  (buf1, sB, sA);
            FSTEP  (buf2, sA, sB);
            FSTEP_R(buf3, sB, sA);
        }
        // tail t = 1021..1023 (prefetch reads rows <= 1027, in bounds)
        FSTEP(buf0, sA, sB);
        FSTEP(buf1, sB, sA);
        FSTEP(buf2, sA, sB);

        g_vecA[b][2 * l] = a.x;
        g_vecA[b][2 * l + 1] = a.y;
        if (l == 0) g_offA[b] = off;
    } else {
        // beta_{2047} = exp(sink)
        a.x = expf(sink[2 * l]);
        a.y = expf(sink[2 * l + 1]);

        float2 buf0 = sp[2047 * 32], buf1 = sp[2046 * 32], buf2 = sp[2045 * 32], buf3 = sp[2044 * 32];
        const float2* pre = sp + 2043 * 32;

        // n = 0..1023: 256 static groups of 4 (prefetch reads rows >= 1020)
        #pragma unroll 1
        for (int grp = 0; grp < 256; grp++) {
            BSTEP  (buf0, sA);
            BSTEP  (buf1, sB);
            BSTEP  (buf2, sA);
            BSTEP_R(buf3, sB);
        }

        g_vecB[b][2 * l] = a.x;
        g_vecB[b][2 * l + 1] = a.y;
        if (l == 0) g_offB[b] = off;
    }
}

// loss_b = log(sum_j A[b][j]*B[b][j]) + offA + offB - gold ; out = mean
__global__ void crf_combine(float* __restrict__ out)
{
    const int b = threadIdx.x;   // 256 threads
    float s = 0.f;
    #pragma unroll
    for (int j = 0; j < NK; j++) s += g_vecA[b][j] * g_vecB[b][j];
    float loss = logf(s) + g_offA[b] + g_offB[b] - g_gold[b];

    __shared__ float red[256];
    red[b] = loss;
    __syncthreads();
    #pragma unroll
    for (int k = 128; k; k >>= 1) {
        if (b < k) red[b] += red[b + k];
        __syncthreads();
    }
    if (b == 0) out[0] = red[0] * (1.0f / NB);
}

extern "C" void kernel_launch(void* const* d_in, const int* in_sizes, int n_in,
                              void* d_out, int out_size)
{
    const float* scores = (const float*)d_in[0];
    const int*   states = (const int*)d_in[1];
    const float* trans  = (const float*)d_in[2];
    const float* source = (const float*)d_in[3];
    const float* sink   = (const float*)d_in[4];

    crf_fused<<<96, 256>>>(scores, states, trans, source, sink);
    crf_combine<<<1, 256>>>((float*)d_out);
}